// round 4
// baseline (speedup 1.0000x reference)
#include <cuda_runtime.h>

// Luong dot attention, fp32 exact.
//   B=8, T=2048, S=2048, D=1024
//   scores = Q@K^T -> softmax rows -> ctx = W@V
// Output buffer layout (tuple flatten): [ctx (B*T*D) | weights (B*T*S)]
// Scores are written straight into the weights region and softmaxed in place,
// so no scratch allocation is needed.

#define B_ 8
#define T_ 2048
#define S_ 2048
#define D_ 1024

// ---------------- packed f32x2 helpers (exact fp32 fma per lane) -------------

__device__ __forceinline__ unsigned long long pk2(float x, float y) {
    unsigned long long r;
    asm("mov.b64 %0, {%1, %2};" : "=l"(r) : "f"(x), "f"(y));
    return r;
}

__device__ __forceinline__ void fma2(unsigned long long& c,
                                     unsigned long long a,
                                     unsigned long long b) {
    asm("fma.rn.f32x2 %0, %1, %2, %0;" : "+l"(c) : "l"(a), "l"(b));
}

__device__ __forceinline__ float2 upk2(unsigned long long v) {
    float2 f;
    asm("mov.b64 {%0, %1}, %2;" : "=f"(f.x), "=f"(f.y) : "l"(v));
    return f;
}

// ---------------- GEMM1: scores[b,t,s] = sum_d trg[b,t,d]*src[b,s,d] (NT) ----
// Tile 128x128, Ktile 16, 256 threads, 8x8 per thread.

__global__ __launch_bounds__(256, 2) void gemm1_nt(
    const float* __restrict__ trg, const float* __restrict__ src,
    float* __restrict__ scores)
{
    __shared__ float As[16][132];
    __shared__ float Bs[16][132];

    const int tid = threadIdx.x;
    const int tx = tid & 15;
    const int ty = tid >> 4;
    const size_t zb = blockIdx.z;

    const float* A  = trg + zb * (size_t)T_ * D_ + (size_t)(blockIdx.y * 128) * D_;
    const float* Bm = src + zb * (size_t)S_ * D_ + (size_t)(blockIdx.x * 128) * D_;
    float*       C  = scores + zb * (size_t)T_ * S_
                    + (size_t)(blockIdx.y * 128) * S_ + blockIdx.x * 128;

    unsigned long long acc[8][4];
    const unsigned long long z0 = pk2(0.0f, 0.0f);
#pragma unroll
    for (int i = 0; i < 8; i++) {
        acc[i][0] = z0; acc[i][1] = z0; acc[i][2] = z0; acc[i][3] = z0;
    }

    const int r0 = tid >> 2;   // 0..63
    const int c4 = tid & 3;    // which float4 of the 16-wide k slice

    for (int k0 = 0; k0 < D_; k0 += 16) {
#pragma unroll
        for (int h = 0; h < 2; h++) {
            const int r = r0 + h * 64;
            float4 va = *(const float4*)(A  + (size_t)r * D_ + k0 + c4 * 4);
            As[c4 * 4 + 0][r] = va.x; As[c4 * 4 + 1][r] = va.y;
            As[c4 * 4 + 2][r] = va.z; As[c4 * 4 + 3][r] = va.w;
            float4 vb = *(const float4*)(Bm + (size_t)r * D_ + k0 + c4 * 4);
            Bs[c4 * 4 + 0][r] = vb.x; Bs[c4 * 4 + 1][r] = vb.y;
            Bs[c4 * 4 + 2][r] = vb.z; Bs[c4 * 4 + 3][r] = vb.w;
        }
        __syncthreads();

#pragma unroll
        for (int k = 0; k < 16; k++) {
            float4 a0 = *(const float4*)&As[k][ty * 8];
            float4 a1 = *(const float4*)&As[k][ty * 8 + 4];
            float4 b0 = *(const float4*)&Bs[k][tx * 8];
            float4 b1 = *(const float4*)&Bs[k][tx * 8 + 4];
            unsigned long long bp0 = pk2(b0.x, b0.y);
            unsigned long long bp1 = pk2(b0.z, b0.w);
            unsigned long long bp2 = pk2(b1.x, b1.y);
            unsigned long long bp3 = pk2(b1.z, b1.w);
            float av[8] = {a0.x, a0.y, a0.z, a0.w, a1.x, a1.y, a1.z, a1.w};
#pragma unroll
            for (int i = 0; i < 8; i++) {
                unsigned long long ap = pk2(av[i], av[i]);
                fma2(acc[i][0], ap, bp0);
                fma2(acc[i][1], ap, bp1);
                fma2(acc[i][2], ap, bp2);
                fma2(acc[i][3], ap, bp3);
            }
        }
        __syncthreads();
    }

    float* Cp = C + (size_t)(ty * 8) * S_ + tx * 8;
#pragma unroll
    for (int i = 0; i < 8; i++) {
        float2 p0 = upk2(acc[i][0]);
        float2 p1 = upk2(acc[i][1]);
        float2 p2 = upk2(acc[i][2]);
        float2 p3 = upk2(acc[i][3]);
        *(float4*)(Cp + (size_t)i * S_)     = make_float4(p0.x, p0.y, p1.x, p1.y);
        *(float4*)(Cp + (size_t)i * S_ + 4) = make_float4(p2.x, p2.y, p3.x, p3.y);
    }
}

// ---------------- softmax over S per (b,t) row, in place ---------------------

__global__ void softmax_rows(float* __restrict__ w)
{
    __shared__ float redm[8];
    __shared__ float reds[8];
    const int tid  = threadIdx.x;
    const int lane = tid & 31;
    const int wid  = tid >> 5;
    float* p = w + (size_t)blockIdx.x * S_;

    float4 v0 = *(const float4*)(p + tid * 4);
    float4 v1 = *(const float4*)(p + 1024 + tid * 4);

    float mx = fmaxf(fmaxf(fmaxf(v0.x, v0.y), fmaxf(v0.z, v0.w)),
                     fmaxf(fmaxf(v1.x, v1.y), fmaxf(v1.z, v1.w)));
#pragma unroll
    for (int o = 16; o; o >>= 1)
        mx = fmaxf(mx, __shfl_xor_sync(0xffffffffu, mx, o));
    if (lane == 0) redm[wid] = mx;
    __syncthreads();
    if (tid < 32) {
        float m = (tid < 8) ? redm[tid] : -3.402823466e38f;
#pragma unroll
        for (int o = 4; o; o >>= 1)
            m = fmaxf(m, __shfl_xor_sync(0xffffffffu, m, o));
        if (tid == 0) redm[0] = m;
    }
    __syncthreads();
    const float bm = redm[0];

    v0.x = expf(v0.x - bm); v0.y = expf(v0.y - bm);
    v0.z = expf(v0.z - bm); v0.w = expf(v0.w - bm);
    v1.x = expf(v1.x - bm); v1.y = expf(v1.y - bm);
    v1.z = expf(v1.z - bm); v1.w = expf(v1.w - bm);

    float s = v0.x + v0.y + v0.z + v0.w + v1.x + v1.y + v1.z + v1.w;
#pragma unroll
    for (int o = 16; o; o >>= 1)
        s += __shfl_xor_sync(0xffffffffu, s, o);
    if (lane == 0) reds[wid] = s;
    __syncthreads();
    if (tid < 32) {
        float t = (tid < 8) ? reds[tid] : 0.0f;
#pragma unroll
        for (int o = 4; o; o >>= 1)
            t += __shfl_xor_sync(0xffffffffu, t, o);
        if (tid == 0) reds[0] = t;
    }
    __syncthreads();
    const float inv = 1.0f / reds[0];

    v0.x *= inv; v0.y *= inv; v0.z *= inv; v0.w *= inv;
    v1.x *= inv; v1.y *= inv; v1.z *= inv; v1.w *= inv;
    *(float4*)(p + tid * 4)        = v0;
    *(float4*)(p + 1024 + tid * 4) = v1;
}

// ---------------- GEMM2: ctx[b,t,d] = sum_s w[b,t,s]*src[b,s,d] (NN) ---------

__global__ __launch_bounds__(256, 2) void gemm2_nn(
    const float* __restrict__ wts, const float* __restrict__ src,
    float* __restrict__ ctx)
{
    __shared__ float As[16][132];
    __shared__ float Bs[16][132];

    const int tid = threadIdx.x;
    const int tx = tid & 15;
    const int ty = tid >> 4;
    const size_t zb = blockIdx.z;

    const float* A  = wts + zb * (size_t)T_ * S_ + (size_t)(blockIdx.y * 128) * S_;
    const float* Bm = src + zb * (size_t)S_ * D_ + blockIdx.x * 128;
    float*       C  = ctx + zb * (size_t)T_ * D_
                    + (size_t)(blockIdx.y * 128) * D_ + blockIdx.x * 128;

    unsigned long long acc[8][4];
    const unsigned long long z0 = pk2(0.0f, 0.0f);
#pragma unroll
    for (int i = 0; i < 8; i++) {
        acc[i][0] = z0; acc[i][1] = z0; acc[i][2] = z0; acc[i][3] = z0;
    }

    const int ra  = tid >> 2;  // A-tile: 0..63, row within M tile
    const int c4  = tid & 3;   // A-tile: float4 within k slice
    const int krb = tid >> 5;  // B-tile: 0..7, k row
    const int nc4 = tid & 31;  // B-tile: float4 within 128-wide n

    for (int k0 = 0; k0 < S_; k0 += 16) {
#pragma unroll
        for (int h = 0; h < 2; h++) {
            const int r = ra + h * 64;
            float4 va = *(const float4*)(A + (size_t)r * S_ + k0 + c4 * 4);
            As[c4 * 4 + 0][r] = va.x; As[c4 * 4 + 1][r] = va.y;
            As[c4 * 4 + 2][r] = va.z; As[c4 * 4 + 3][r] = va.w;
            const int kr = krb + h * 8;
            float4 vb = *(const float4*)(Bm + (size_t)(k0 + kr) * D_ + nc4 * 4);
            *(float4*)&Bs[kr][nc4 * 4] = vb;
        }
        __syncthreads();

#pragma unroll
        for (int k = 0; k < 16; k++) {
            float4 a0 = *(const float4*)&As[k][ty * 8];
            float4 a1 = *(const float4*)&As[k][ty * 8 + 4];
            float4 b0 = *(const float4*)&Bs[k][tx * 8];
            float4 b1 = *(const float4*)&Bs[k][tx * 8 + 4];
            unsigned long long bp0 = pk2(b0.x, b0.y);
            unsigned long long bp1 = pk2(b0.z, b0.w);
            unsigned long long bp2 = pk2(b1.x, b1.y);
            unsigned long long bp3 = pk2(b1.z, b1.w);
            float av[8] = {a0.x, a0.y, a0.z, a0.w, a1.x, a1.y, a1.z, a1.w};
#pragma unroll
            for (int i = 0; i < 8; i++) {
                unsigned long long ap = pk2(av[i], av[i]);
                fma2(acc[i][0], ap, bp0);
                fma2(acc[i][1], ap, bp1);
                fma2(acc[i][2], ap, bp2);
                fma2(acc[i][3], ap, bp3);
            }
        }
        __syncthreads();
    }

    float* Cp = C + (size_t)(ty * 8) * D_ + tx * 8;
#pragma unroll
    for (int i = 0; i < 8; i++) {
        float2 p0 = upk2(acc[i][0]);
        float2 p1 = upk2(acc[i][1]);
        float2 p2 = upk2(acc[i][2]);
        float2 p3 = upk2(acc[i][3]);
        *(float4*)(Cp + (size_t)i * D_)     = make_float4(p0.x, p0.y, p1.x, p1.y);
        *(float4*)(Cp + (size_t)i * D_ + 4) = make_float4(p2.x, p2.y, p3.x, p3.y);
    }
}

// ---------------- launch -----------------------------------------------------

extern "C" void kernel_launch(void* const* d_in, const int* in_sizes, int n_in,
                              void* d_out, int out_size)
{
    const float* trg = (const float*)d_in[0];   // (B, T, D)
    const float* src = (const float*)d_in[1];   // (B, S, D)
    float* ctx = (float*)d_out;                           // (B, T, D)
    float* wts = (float*)d_out + (size_t)B_ * T_ * D_;    // (B, T, S)

    dim3 g1(S_ / 128, T_ / 128, B_);
    gemm1_nt<<<g1, 256>>>(trg, src, wts);

    softmax_rows<<<B_ * T_, 256>>>(wts);

    dim3 g2(D_ / 128, T_ / 128, B_);
    gemm2_nn<<<g2, 256>>>(wts, src, ctx);
}

// round 5
// speedup vs baseline: 1.2032x; 1.2032x over previous
#include <cuda_runtime.h>

// Luong dot attention, fp32 exact.
//   B=8, T=2048, S=2048, D=1024
//   scores = Q@K^T -> softmax rows -> ctx = W@V
// Output layout (tuple flatten): [ctx (B*T*D) | weights (B*T*S)]
// Scores go straight into the weights region and are softmaxed in place.

#define B_ 8
#define T_ 2048
#define S_ 2048
#define D_ 1024

// ---------------- packed f32x2 helpers (exact fp32 fma per lane) -------------

__device__ __forceinline__ unsigned long long pk2(float x, float y) {
    unsigned long long r;
    asm("mov.b64 %0, {%1, %2};" : "=l"(r) : "f"(x), "f"(y));
    return r;
}

__device__ __forceinline__ void fma2(unsigned long long& c,
                                     unsigned long long a,
                                     unsigned long long b) {
    asm("fma.rn.f32x2 %0, %1, %2, %0;" : "+l"(c) : "l"(a), "l"(b));
}

__device__ __forceinline__ float2 upk2(unsigned long long v) {
    float2 f;
    asm("mov.b64 {%0, %1}, %2;" : "=f"(f.x), "=f"(f.y) : "l"(v));
    return f;
}

// Shared compute step: 16-k rank-1 updates on one buffer.
// Fragment layout: rows ty*8..+7 ; cols {tx*4..+3} U {64+tx*4..+3}
// (4-float column runs -> consecutive tx stride 16B -> conflict-free LDS.128)
#define COMPUTE_TILE(AS, BS)                                                  \
    _Pragma("unroll")                                                         \
    for (int k = 0; k < 16; k++) {                                            \
        float4 a0 = *(const float4*)&AS[k][ty * 8];                           \
        float4 a1 = *(const float4*)&AS[k][ty * 8 + 4];                       \
        float4 b0 = *(const float4*)&BS[k][tx * 4];                           \
        float4 b1 = *(const float4*)&BS[k][64 + tx * 4];                      \
        unsigned long long bp0 = pk2(b0.x, b0.y);                             \
        unsigned long long bp1 = pk2(b0.z, b0.w);                             \
        unsigned long long bp2 = pk2(b1.x, b1.y);                             \
        unsigned long long bp3 = pk2(b1.z, b1.w);                             \
        float av[8] = {a0.x, a0.y, a0.z, a0.w, a1.x, a1.y, a1.z, a1.w};       \
        _Pragma("unroll")                                                     \
        for (int i = 0; i < 8; i++) {                                         \
            unsigned long long ap = pk2(av[i], av[i]);                        \
            fma2(acc[i][0], ap, bp0);                                         \
            fma2(acc[i][1], ap, bp1);                                         \
            fma2(acc[i][2], ap, bp2);                                         \
            fma2(acc[i][3], ap, bp3);                                         \
        }                                                                     \
    }

// ---------------- GEMM1: scores[b,t,s] = sum_d trg[b,t,d]*src[b,s,d] (NT) ----
// 128x128 tile, Ktile 16, 256 threads, 8x8 per thread, smem double-buffered.

__global__ __launch_bounds__(256, 2) void gemm1_nt(
    const float* __restrict__ trg, const float* __restrict__ src,
    float* __restrict__ scores)
{
    __shared__ float As[2][16][132];
    __shared__ float Bs[2][16][132];

    const int tid = threadIdx.x;
    const int tx = tid & 15;
    const int ty = tid >> 4;
    const size_t zb = blockIdx.z;

    const float* A  = trg + zb * (size_t)T_ * D_ + (size_t)(blockIdx.y * 128) * D_;
    const float* Bm = src + zb * (size_t)S_ * D_ + (size_t)(blockIdx.x * 128) * D_;
    float*       C  = scores + zb * (size_t)T_ * S_
                    + (size_t)(blockIdx.y * 128) * S_ + blockIdx.x * 128;

    const int r0 = tid >> 2;   // 0..63
    const int c4 = tid & 3;    // which float4 of the 16-wide k slice

    float4 pa[2], pb[2];
#pragma unroll
    for (int h = 0; h < 2; h++) {
        const int r = r0 + h * 64;
        pa[h] = *(const float4*)(A  + (size_t)r * D_ + c4 * 4);
        pb[h] = *(const float4*)(Bm + (size_t)r * D_ + c4 * 4);
    }
#pragma unroll
    for (int h = 0; h < 2; h++) {
        const int r = r0 + h * 64;
        As[0][c4 * 4 + 0][r] = pa[h].x; As[0][c4 * 4 + 1][r] = pa[h].y;
        As[0][c4 * 4 + 2][r] = pa[h].z; As[0][c4 * 4 + 3][r] = pa[h].w;
        Bs[0][c4 * 4 + 0][r] = pb[h].x; Bs[0][c4 * 4 + 1][r] = pb[h].y;
        Bs[0][c4 * 4 + 2][r] = pb[h].z; Bs[0][c4 * 4 + 3][r] = pb[h].w;
    }
    __syncthreads();

    unsigned long long acc[8][4];
    const unsigned long long z0 = pk2(0.0f, 0.0f);
#pragma unroll
    for (int i = 0; i < 8; i++) {
        acc[i][0] = z0; acc[i][1] = z0; acc[i][2] = z0; acc[i][3] = z0;
    }

    int s = 0;
    for (int k0 = 0; k0 < D_; k0 += 16) {
        const int kn = k0 + 16;
        if (kn < D_) {
#pragma unroll
            for (int h = 0; h < 2; h++) {
                const int r = r0 + h * 64;
                pa[h] = *(const float4*)(A  + (size_t)r * D_ + kn + c4 * 4);
                pb[h] = *(const float4*)(Bm + (size_t)r * D_ + kn + c4 * 4);
            }
        }

        if (s == 0) { COMPUTE_TILE(As[0], Bs[0]) } else { COMPUTE_TILE(As[1], Bs[1]) }

        if (kn < D_) {
            const int d = s ^ 1;
#pragma unroll
            for (int h = 0; h < 2; h++) {
                const int r = r0 + h * 64;
                As[d][c4 * 4 + 0][r] = pa[h].x; As[d][c4 * 4 + 1][r] = pa[h].y;
                As[d][c4 * 4 + 2][r] = pa[h].z; As[d][c4 * 4 + 3][r] = pa[h].w;
                Bs[d][c4 * 4 + 0][r] = pb[h].x; Bs[d][c4 * 4 + 1][r] = pb[h].y;
                Bs[d][c4 * 4 + 2][r] = pb[h].z; Bs[d][c4 * 4 + 3][r] = pb[h].w;
            }
            __syncthreads();
            s = d;
        }
    }

    float* Cp = C + (size_t)(ty * 8) * S_ + tx * 4;
#pragma unroll
    for (int i = 0; i < 8; i++) {
        float2 p0 = upk2(acc[i][0]);
        float2 p1 = upk2(acc[i][1]);
        float2 p2 = upk2(acc[i][2]);
        float2 p3 = upk2(acc[i][3]);
        *(float4*)(Cp + (size_t)i * S_)      = make_float4(p0.x, p0.y, p1.x, p1.y);
        *(float4*)(Cp + (size_t)i * S_ + 64) = make_float4(p2.x, p2.y, p3.x, p3.y);
    }
}

// ---------------- softmax over S per (b,t) row, in place ---------------------

__global__ void softmax_rows(float* __restrict__ w)
{
    __shared__ float redm[8];
    __shared__ float reds[8];
    const int tid  = threadIdx.x;
    const int lane = tid & 31;
    const int wid  = tid >> 5;
    float* p = w + (size_t)blockIdx.x * S_;

    float4 v0 = *(const float4*)(p + tid * 4);
    float4 v1 = *(const float4*)(p + 1024 + tid * 4);

    float mx = fmaxf(fmaxf(fmaxf(v0.x, v0.y), fmaxf(v0.z, v0.w)),
                     fmaxf(fmaxf(v1.x, v1.y), fmaxf(v1.z, v1.w)));
#pragma unroll
    for (int o = 16; o; o >>= 1)
        mx = fmaxf(mx, __shfl_xor_sync(0xffffffffu, mx, o));
    if (lane == 0) redm[wid] = mx;
    __syncthreads();
    if (tid < 32) {
        float m = (tid < 8) ? redm[tid] : -3.402823466e38f;
#pragma unroll
        for (int o = 4; o; o >>= 1)
            m = fmaxf(m, __shfl_xor_sync(0xffffffffu, m, o));
        if (tid == 0) redm[0] = m;
    }
    __syncthreads();
    const float bm = redm[0];

    v0.x = __expf(v0.x - bm); v0.y = __expf(v0.y - bm);
    v0.z = __expf(v0.z - bm); v0.w = __expf(v0.w - bm);
    v1.x = __expf(v1.x - bm); v1.y = __expf(v1.y - bm);
    v1.z = __expf(v1.z - bm); v1.w = __expf(v1.w - bm);

    float sm = v0.x + v0.y + v0.z + v0.w + v1.x + v1.y + v1.z + v1.w;
#pragma unroll
    for (int o = 16; o; o >>= 1)
        sm += __shfl_xor_sync(0xffffffffu, sm, o);
    if (lane == 0) reds[wid] = sm;
    __syncthreads();
    if (tid < 32) {
        float t = (tid < 8) ? reds[tid] : 0.0f;
#pragma unroll
        for (int o = 4; o; o >>= 1)
            t += __shfl_xor_sync(0xffffffffu, t, o);
        if (tid == 0) reds[0] = t;
    }
    __syncthreads();
    const float inv = 1.0f / reds[0];

    v0.x *= inv; v0.y *= inv; v0.z *= inv; v0.w *= inv;
    v1.x *= inv; v1.y *= inv; v1.z *= inv; v1.w *= inv;
    *(float4*)(p + tid * 4)        = v0;
    *(float4*)(p + 1024 + tid * 4) = v1;
}

// ---------------- GEMM2: ctx[b,t,d] = sum_s w[b,t,s]*src[b,s,d] (NN) ---------

__global__ __launch_bounds__(256, 2) void gemm2_nn(
    const float* __restrict__ wts, const float* __restrict__ src,
    float* __restrict__ ctx)
{
    __shared__ float As[2][16][132];
    __shared__ float Bs[2][16][132];

    const int tid = threadIdx.x;
    const int tx = tid & 15;
    const int ty = tid >> 4;
    const size_t zb = blockIdx.z;

    const float* A  = wts + zb * (size_t)T_ * S_ + (size_t)(blockIdx.y * 128) * S_;
    const float* Bm = src + zb * (size_t)S_ * D_ + blockIdx.x * 128;
    float*       C  = ctx + zb * (size_t)T_ * D_
                    + (size_t)(blockIdx.y * 128) * D_ + blockIdx.x * 128;

    const int ra  = tid >> 2;  // A-tile row 0..63
    const int c4  = tid & 3;   // A-tile float4 within k slice
    const int krb = tid >> 5;  // B-tile k row 0..7
    const int nc4 = tid & 31;  // B-tile float4 within 128-wide n

    float4 pa[2], pb[2];
#pragma unroll
    for (int h = 0; h < 2; h++) {
        pa[h] = *(const float4*)(A + (size_t)(ra + h * 64) * S_ + c4 * 4);
        pb[h] = *(const float4*)(Bm + (size_t)(krb + h * 8) * D_ + nc4 * 4);
    }
#pragma unroll
    for (int h = 0; h < 2; h++) {
        const int r = ra + h * 64;
        As[0][c4 * 4 + 0][r] = pa[h].x; As[0][c4 * 4 + 1][r] = pa[h].y;
        As[0][c4 * 4 + 2][r] = pa[h].z; As[0][c4 * 4 + 3][r] = pa[h].w;
        *(float4*)&Bs[0][krb + h * 8][nc4 * 4] = pb[h];
    }
    __syncthreads();

    unsigned long long acc[8][4];
    const unsigned long long z0 = pk2(0.0f, 0.0f);
#pragma unroll
    for (int i = 0; i < 8; i++) {
        acc[i][0] = z0; acc[i][1] = z0; acc[i][2] = z0; acc[i][3] = z0;
    }

    int s = 0;
    for (int k0 = 0; k0 < S_; k0 += 16) {
        const int kn = k0 + 16;
        if (kn < S_) {
#pragma unroll
            for (int h = 0; h < 2; h++) {
                pa[h] = *(const float4*)(A + (size_t)(ra + h * 64) * S_ + kn + c4 * 4);
                pb[h] = *(const float4*)(Bm + (size_t)(kn + krb + h * 8) * D_ + nc4 * 4);
            }
        }

        if (s == 0) { COMPUTE_TILE(As[0], Bs[0]) } else { COMPUTE_TILE(As[1], Bs[1]) }

        if (kn < S_) {
            const int d = s ^ 1;
#pragma unroll
            for (int h = 0; h < 2; h++) {
                const int r = ra + h * 64;
                As[d][c4 * 4 + 0][r] = pa[h].x; As[d][c4 * 4 + 1][r] = pa[h].y;
                As[d][c4 * 4 + 2][r] = pa[h].z; As[d][c4 * 4 + 3][r] = pa[h].w;
                *(float4*)&Bs[d][krb + h * 8][nc4 * 4] = pb[h];
            }
            __syncthreads();
            s = d;
        }
    }

    float* Cp = C + (size_t)(ty * 8) * D_ + tx * 4;
#pragma unroll
    for (int i = 0; i < 8; i++) {
        float2 p0 = upk2(acc[i][0]);
        float2 p1 = upk2(acc[i][1]);
        float2 p2 = upk2(acc[i][2]);
        float2 p3 = upk2(acc[i][3]);
        *(float4*)(Cp + (size_t)i * D_)      = make_float4(p0.x, p0.y, p1.x, p1.y);
        *(float4*)(Cp + (size_t)i * D_ + 64) = make_float4(p2.x, p2.y, p3.x, p3.y);
    }
}

// ---------------- launch -----------------------------------------------------

extern "C" void kernel_launch(void* const* d_in, const int* in_sizes, int n_in,
                              void* d_out, int out_size)
{
    const float* trg = (const float*)d_in[0];   // (B, T, D)
    const float* src = (const float*)d_in[1];   // (B, S, D)
    float* ctx = (float*)d_out;                           // (B, T, D)
    float* wts = (float*)d_out + (size_t)B_ * T_ * D_;    // (B, T, S)

    dim3 g1(S_ / 128, T_ / 128, B_);
    gemm1_nt<<<g1, 256>>>(trg, src, wts);

    softmax_rows<<<B_ * T_, 256>>>(wts);

    dim3 g2(D_ / 128, T_ / 128, B_);
    gemm2_nn<<<g2, 256>>>(wts, src, ctx);
}

// round 7
// speedup vs baseline: 1.3110x; 1.0896x over previous
#include <cuda_runtime.h>
#include <cstdint>

// Luong dot attention via mma.sync.m16n8k8.tf32 (baseline PTX, runs on the
// Blackwell legacy HMMA path -- tcgen05 is compiler-blocked here), with a
// 3xTF32 error-compensated split for fp32-grade accuracy.
//   B=8, T=2048, S=2048, D=1024
//   scores = Q@K^T -> softmax rows -> ctx = W@V
// Output layout: [ctx (B*T*D) | weights (B*T*S)]; scores built in place in the
// weights region. Scratch: V^T (B,D,S) fp32 in a __device__ global (64MB).

#define B_ 8
#define T_ 2048
#define S_ 2048
#define D_ 1024

__device__ __align__(128) float g_vT[(size_t)B_ * D_ * S_];   // 64 MB scratch

// ---------------------------------------------------------------- PTX helpers

__device__ __forceinline__ uint32_t smem_u32(const void* p) {
    uint32_t a;
    asm("{ .reg .u64 t; cvta.to.shared.u64 t, %1; cvt.u32.u64 %0, t; }"
        : "=r"(a) : "l"(p));
    return a;
}

#define LDSM4(r0, r1, r2, r3, addr)                                            \
    asm volatile("ldmatrix.sync.aligned.m8n8.x4.shared.b16 {%0,%1,%2,%3}, [%4];" \
                 : "=r"(r0), "=r"(r1), "=r"(r2), "=r"(r3) : "r"(addr))

#define MMA_TF32(c, a, b)                                                      \
    asm volatile("mma.sync.aligned.m16n8k8.row.col.f32.tf32.tf32.f32 "         \
                 "{%0,%1,%2,%3}, {%4,%5,%6,%7}, {%8,%9}, {%0,%1,%2,%3};"       \
                 : "+f"((c)[0]), "+f"((c)[1]), "+f"((c)[2]), "+f"((c)[3])      \
                 : "r"((a)[0]), "r"((a)[1]), "r"((a)[2]), "r"((a)[3]),         \
                   "r"((b)[0]), "r"((b)[1]))

__device__ __forceinline__ uint32_t tf32_rna(float f) {
    uint32_t r;
    asm("cvt.rna.tf32.f32 %0, %1;" : "=r"(r) : "f"(f));
    return r;
}

__device__ __forceinline__ float hi_mask(float v) {
    return __uint_as_float(__float_as_uint(v) & 0xFFFFE000u);  // 10 mant bits
}

// ---------------------------------------------------------------- GEMM kernel
// C[M,N] = A[M,K] * B[N,K]^T, fp32 K-major inputs, tf32x3 split on the fly.
// CTA tile 128x128, K-chunk 32, 256 threads (8 warps, warp tile 64x32).
// Smem: 2 stages x { AHI 16K | ALO 16K | BHI 16K | BLO 16K } = 128 KB.

#define OFF_AHI 0
#define OFF_ALO 16384
#define OFF_BHI 32768
#define OFF_BLO 49152
#define STAGE_BYTES 65536
#define SMEM_TOTAL (2 * STAGE_BYTES)

__global__ __launch_bounds__(256, 1) void gemm_tf32x3(
    const float* __restrict__ Ag, const float* __restrict__ Bg,
    float* __restrict__ Cg, int lda, int ldb, int ldc, int K,
    size_t strideA, size_t strideB, size_t strideC)
{
    extern __shared__ char smem[];
    const uint32_t sb = smem_u32(smem);
    const int tid  = threadIdx.x;
    const int wid  = tid >> 5;
    const int lane = tid & 31;
    const size_t z = blockIdx.z;

    const float* A  = Ag + z * strideA + (size_t)(blockIdx.y * 128) * lda;
    const float* Bm = Bg + z * strideB + (size_t)(blockIdx.x * 128) * ldb;
    float*       C  = Cg + z * strideC + (size_t)(blockIdx.y * 128) * ldc
                    + blockIdx.x * 128;

    const int warp_m = (wid & 1) * 64;
    const int warp_n = (wid >> 1) * 32;

    // ldmatrix thread geometry (tile = which 8x8 sub-matrix this lane feeds)
    const int tile = lane >> 3;
    const int l8   = lane & 7;
    const int a_row0   = warp_m + ((tile & 1) << 3) + l8;  // + mi*16
    const int a_k4sel  = tile >> 1;
    const int b_row0   = warp_n + ((tile >> 1) << 3) + l8; // + nj*16
    const int b_k4sel  = tile & 1;

    float acc[4][4][4];
#pragma unroll
    for (int i = 0; i < 4; i++)
#pragma unroll
        for (int j = 0; j < 4; j++) {
            acc[i][j][0] = 0.f; acc[i][j][1] = 0.f;
            acc[i][j][2] = 0.f; acc[i][j][3] = 0.f;
        }

    float4 ra[4], rb[4];

// Load one 128x32 chunk of A and B (4 float4 each per thread).
#define LDG_CHUNK(K0)                                                          \
    _Pragma("unroll")                                                          \
    for (int j = 0; j < 4; j++) {                                              \
        int idx = tid + 256 * j;                                               \
        int row = idx >> 3, seg = idx & 7;                                     \
        ra[j] = *(const float4*)(A  + (size_t)row * lda + (K0) + seg * 4);     \
        rb[j] = *(const float4*)(Bm + (size_t)row * ldb + (K0) + seg * 4);     \
    }

// Split + swizzled store into stage ST (char* base of stage).
#define STS_CHUNK(ST)                                                          \
    _Pragma("unroll")                                                          \
    for (int j = 0; j < 4; j++) {                                              \
        int idx = tid + 256 * j;                                               \
        int row = idx >> 3, seg = idx & 7;                                     \
        uint32_t off = ((uint32_t)row << 7) | ((uint32_t)seg << 4);            \
        off ^= (off >> 3) & 0x70;                                              \
        float4 ah4, bh4; uint4 al4, bl4;                                       \
        ah4.x = hi_mask(ra[j].x); ah4.y = hi_mask(ra[j].y);                    \
        ah4.z = hi_mask(ra[j].z); ah4.w = hi_mask(ra[j].w);                    \
        al4.x = tf32_rna(ra[j].x - ah4.x); al4.y = tf32_rna(ra[j].y - ah4.y);  \
        al4.z = tf32_rna(ra[j].z - ah4.z); al4.w = tf32_rna(ra[j].w - ah4.w);  \
        bh4.x = hi_mask(rb[j].x); bh4.y = hi_mask(rb[j].y);                    \
        bh4.z = hi_mask(rb[j].z); bh4.w = hi_mask(rb[j].w);                    \
        bl4.x = tf32_rna(rb[j].x - bh4.x); bl4.y = tf32_rna(rb[j].y - bh4.y);  \
        bl4.z = tf32_rna(rb[j].z - bh4.z); bl4.w = tf32_rna(rb[j].w - bh4.w);  \
        *(float4*)((ST) + OFF_AHI + off) = ah4;                                \
        *(uint4*) ((ST) + OFF_ALO + off) = al4;                                \
        *(float4*)((ST) + OFF_BHI + off) = bh4;                                \
        *(uint4*) ((ST) + OFF_BLO + off) = bl4;                                \
    }

    // Prologue: chunk 0 -> stage 0
    LDG_CHUNK(0)
    STS_CHUNK(smem)
    __syncthreads();

    const int nc = K / 32;

    for (int i = 0; i < nc; i++) {
        const uint32_t st = sb + (uint32_t)(i & 1) * STAGE_BYTES;

        if (i + 1 < nc) { LDG_CHUNK((i + 1) * 32) }

        // Compute chunk i: 4 k-slices of 8
#pragma unroll
        for (int ks = 0; ks < 4; ks++) {
            uint32_t ah[4][4], al[4][4], bh[4][2], bl[4][2];
#pragma unroll
            for (int mi = 0; mi < 4; mi++) {
                int row = a_row0 + mi * 16;
                uint32_t off = ((uint32_t)row << 7)
                             | ((uint32_t)((ks * 2 + a_k4sel) << 4) ^ ((row & 7) << 4));
                LDSM4(ah[mi][0], ah[mi][1], ah[mi][2], ah[mi][3],
                      st + OFF_AHI + off);
                LDSM4(al[mi][0], al[mi][1], al[mi][2], al[mi][3],
                      st + OFF_ALO + off);
            }
#pragma unroll
            for (int nj = 0; nj < 2; nj++) {
                int row = b_row0 + nj * 16;
                uint32_t off = ((uint32_t)row << 7)
                             | ((uint32_t)((ks * 2 + b_k4sel) << 4) ^ ((row & 7) << 4));
                LDSM4(bh[nj * 2][0], bh[nj * 2][1], bh[nj * 2 + 1][0], bh[nj * 2 + 1][1],
                      st + OFF_BHI + off);
                LDSM4(bl[nj * 2][0], bl[nj * 2][1], bl[nj * 2 + 1][0], bl[nj * 2 + 1][1],
                      st + OFF_BLO + off);
            }
            // term-outermost: same-accum MMAs are 16 apart
#pragma unroll
            for (int mi = 0; mi < 4; mi++)
#pragma unroll
                for (int ni = 0; ni < 4; ni++)
                    MMA_TF32(acc[mi][ni], ah[mi], bh[ni]);
#pragma unroll
            for (int mi = 0; mi < 4; mi++)
#pragma unroll
                for (int ni = 0; ni < 4; ni++)
                    MMA_TF32(acc[mi][ni], ah[mi], bl[ni]);
#pragma unroll
            for (int mi = 0; mi < 4; mi++)
#pragma unroll
                for (int ni = 0; ni < 4; ni++)
                    MMA_TF32(acc[mi][ni], al[mi], bh[ni]);
        }

        if (i + 1 < nc) {
            char* stn = smem + ((i + 1) & 1) * STAGE_BYTES;
            STS_CHUNK(stn)
            __syncthreads();
        }
    }

    // Epilogue: write accumulators (c0,c1 @ row, c2,c3 @ row+8)
    const int erow = warp_m + (lane >> 2);
    const int ecol = warp_n + 2 * (lane & 3);
#pragma unroll
    for (int mi = 0; mi < 4; mi++) {
#pragma unroll
        for (int ni = 0; ni < 4; ni++) {
            float* cp = C + (size_t)(erow + mi * 16) * ldc + ecol + ni * 8;
            *(float2*)cp = make_float2(acc[mi][ni][0], acc[mi][ni][1]);
            *(float2*)(cp + (size_t)8 * ldc) = make_float2(acc[mi][ni][2], acc[mi][ni][3]);
        }
    }
}

// ---------------------------------------------------------------- transpose
// vT[b][d][s] = src[b][s][d]

__global__ void transpose_bsd(const float* __restrict__ src, float* __restrict__ dst)
{
    __shared__ float t[32][33];
    const int b = blockIdx.z;
    const int s0 = blockIdx.x * 32;
    const int d0 = blockIdx.y * 32;
    const float* sp = src + (size_t)b * S_ * D_;
    float* dp = dst + (size_t)b * D_ * S_;
    const int tx = threadIdx.x, ty = threadIdx.y;
#pragma unroll
    for (int i = 0; i < 32; i += 8)
        t[ty + i][tx] = sp[(size_t)(s0 + ty + i) * D_ + d0 + tx];
    __syncthreads();
#pragma unroll
    for (int i = 0; i < 32; i += 8)
        dp[(size_t)(d0 + ty + i) * S_ + s0 + tx] = t[tx][ty + i];
}

// ---------------------------------------------------------------- softmax

__global__ void softmax_rows(float* __restrict__ w)
{
    __shared__ float redm[8];
    __shared__ float reds[8];
    const int tid  = threadIdx.x;
    const int lane = tid & 31;
    const int wid  = tid >> 5;
    float* p = w + (size_t)blockIdx.x * S_;

    float4 v0 = *(const float4*)(p + tid * 4);
    float4 v1 = *(const float4*)(p + 1024 + tid * 4);

    float mx = fmaxf(fmaxf(fmaxf(v0.x, v0.y), fmaxf(v0.z, v0.w)),
                     fmaxf(fmaxf(v1.x, v1.y), fmaxf(v1.z, v1.w)));
#pragma unroll
    for (int o = 16; o; o >>= 1)
        mx = fmaxf(mx, __shfl_xor_sync(0xffffffffu, mx, o));
    if (lane == 0) redm[wid] = mx;
    __syncthreads();
    if (tid < 32) {
        float m = (tid < 8) ? redm[tid] : -3.402823466e38f;
#pragma unroll
        for (int o = 4; o; o >>= 1)
            m = fmaxf(m, __shfl_xor_sync(0xffffffffu, m, o));
        if (tid == 0) redm[0] = m;
    }
    __syncthreads();
    const float bm = redm[0];

    v0.x = __expf(v0.x - bm); v0.y = __expf(v0.y - bm);
    v0.z = __expf(v0.z - bm); v0.w = __expf(v0.w - bm);
    v1.x = __expf(v1.x - bm); v1.y = __expf(v1.y - bm);
    v1.z = __expf(v1.z - bm); v1.w = __expf(v1.w - bm);

    float sm = v0.x + v0.y + v0.z + v0.w + v1.x + v1.y + v1.z + v1.w;
#pragma unroll
    for (int o = 16; o; o >>= 1)
        sm += __shfl_xor_sync(0xffffffffu, sm, o);
    if (lane == 0) reds[wid] = sm;
    __syncthreads();
    if (tid < 32) {
        float t = (tid < 8) ? reds[tid] : 0.0f;
#pragma unroll
        for (int o = 4; o; o >>= 1)
            t += __shfl_xor_sync(0xffffffffu, t, o);
        if (tid == 0) reds[0] = t;
    }
    __syncthreads();
    const float inv = 1.0f / reds[0];

    v0.x *= inv; v0.y *= inv; v0.z *= inv; v0.w *= inv;
    v1.x *= inv; v1.y *= inv; v1.z *= inv; v1.w *= inv;
    *(float4*)(p + tid * 4)        = v0;
    *(float4*)(p + 1024 + tid * 4) = v1;
}

// ---------------------------------------------------------------- launch

extern "C" void kernel_launch(void* const* d_in, const int* in_sizes, int n_in,
                              void* d_out, int out_size)
{
    const float* trg = (const float*)d_in[0];   // (B, T, D)
    const float* src = (const float*)d_in[1];   // (B, S, D)
    float* ctx = (float*)d_out;                           // (B, T, D)
    float* wts = (float*)d_out + (size_t)B_ * T_ * D_;    // (B, T, S)

    void* vTp = nullptr;
    cudaGetSymbolAddress(&vTp, g_vT);
    float* vT = (float*)vTp;

    cudaFuncSetAttribute(gemm_tf32x3,
                         cudaFuncAttributeMaxDynamicSharedMemorySize, SMEM_TOTAL);

    // 1) vT = transpose(src)
    transpose_bsd<<<dim3(S_ / 32, D_ / 32, B_), dim3(32, 8)>>>(src, vT);

    // 2) scores = trg @ src^T   (A=trg [T,D], B=src [S,D], both K-major)
    gemm_tf32x3<<<dim3(S_ / 128, T_ / 128, B_), 256, SMEM_TOTAL>>>(
        trg, src, wts, D_, D_, S_, D_,
        (size_t)T_ * D_, (size_t)S_ * D_, (size_t)T_ * S_);

    // 3) softmax rows in place
    softmax_rows<<<B_ * T_, 256>>>(wts);

    // 4) ctx = wts @ vT^T   (A=wts [T,S], B=vT [D,S], both K-major)
    gemm_tf32x3<<<dim3(D_ / 128, T_ / 128, B_), 256, SMEM_TOTAL>>>(
        wts, vT, ctx, S_, S_, D_, S_,
        (size_t)T_ * S_, (size_t)D_ * S_, (size_t)T_ * D_);
}

// round 8
// speedup vs baseline: 2.5946x; 1.9791x over previous
#include <cuda_runtime.h>
#include <cuda_fp16.h>
#include <cstdint>

// Luong dot attention via mma.sync.m16n8k16.f16.f32 (baseline PTX, Blackwell
// legacy HMMA path), 3-term error-compensated FP16 split (hh + hl + lh).
//   B=8, T=2048, S=2048, D=1024
//   scores = Q@K^T -> softmax rows -> ctx = W@V
// Output layout: [ctx (B*T*D) | weights (B*T*S)]; scores built in place in the
// weights region. Scratch: V^T (B,D,S) fp32 in a __device__ global (64MB).

#define B_ 8
#define T_ 2048
#define S_ 2048
#define D_ 1024

__device__ __align__(128) float g_vT[(size_t)B_ * D_ * S_];   // 64 MB scratch

// ---------------------------------------------------------------- PTX helpers

__device__ __forceinline__ uint32_t smem_u32(const void* p) {
    uint32_t a;
    asm("{ .reg .u64 t; cvta.to.shared.u64 t, %1; cvt.u32.u64 %0, t; }"
        : "=r"(a) : "l"(p));
    return a;
}

#define LDSM4(r0, r1, r2, r3, addr)                                            \
    asm volatile("ldmatrix.sync.aligned.m8n8.x4.shared.b16 {%0,%1,%2,%3}, [%4];" \
                 : "=r"(r0), "=r"(r1), "=r"(r2), "=r"(r3) : "r"(addr))

#define MMA_F16(c, a, b)                                                       \
    asm volatile("mma.sync.aligned.m16n8k16.row.col.f32.f16.f16.f32 "          \
                 "{%0,%1,%2,%3}, {%4,%5,%6,%7}, {%8,%9}, {%0,%1,%2,%3};"       \
                 : "+f"((c)[0]), "+f"((c)[1]), "+f"((c)[2]), "+f"((c)[3])      \
                 : "r"((a)[0]), "r"((a)[1]), "r"((a)[2]), "r"((a)[3]),         \
                   "r"((b)[0]), "r"((b)[1]))

// Split a float4 into fp16 hi (rn) and fp16 lo (residual), packed as 2x half2.
__device__ __forceinline__ void split4(float4 v, uint2& hi, uint2& lo) {
    __half2 h0 = __floats2half2_rn(v.x, v.y);
    __half2 h1 = __floats2half2_rn(v.z, v.w);
    float2 f0 = __half22float2(h0);
    float2 f1 = __half22float2(h1);
    __half2 l0 = __floats2half2_rn(v.x - f0.x, v.y - f0.y);
    __half2 l1 = __floats2half2_rn(v.z - f1.x, v.w - f1.y);
    hi.x = *reinterpret_cast<uint32_t*>(&h0);
    hi.y = *reinterpret_cast<uint32_t*>(&h1);
    lo.x = *reinterpret_cast<uint32_t*>(&l0);
    lo.y = *reinterpret_cast<uint32_t*>(&l1);
}

// ---------------------------------------------------------------- GEMM kernel
// C[M,N] = A[M,K] * B[N,K]^T, fp32 K-major inputs, fp16x3 split on the fly.
// CTA tile 128x128, K-chunk 64, 256 threads (8 warps, warp tile 64x32).
// Smem rows: 64 halves = 128B, SW128 xor swizzle (same pattern as validated
// tf32 kernel). 2 stages x { AHI 16K | ALO 16K | BHI 16K | BLO 16K } = 128 KB.

#define OFF_AHI 0
#define OFF_ALO 16384
#define OFF_BHI 32768
#define OFF_BLO 49152
#define STAGE_BYTES 65536
#define SMEM_TOTAL (2 * STAGE_BYTES)

__global__ __launch_bounds__(256, 1) void gemm_f16x3(
    const float* __restrict__ Ag, const float* __restrict__ Bg,
    float* __restrict__ Cg, int lda, int ldb, int ldc, int K,
    size_t strideA, size_t strideB, size_t strideC)
{
    extern __shared__ char smem[];
    const uint32_t sb = smem_u32(smem);
    const int tid  = threadIdx.x;
    const int wid  = tid >> 5;
    const int lane = tid & 31;
    const size_t z = blockIdx.z;

    const float* A  = Ag + z * strideA + (size_t)(blockIdx.y * 128) * lda;
    const float* Bm = Bg + z * strideB + (size_t)(blockIdx.x * 128) * ldb;
    float*       C  = Cg + z * strideC + (size_t)(blockIdx.y * 128) * ldc
                    + blockIdx.x * 128;

    const int warp_m = (wid & 1) * 64;
    const int warp_n = (wid >> 1) * 32;

    // ldmatrix thread geometry (tile = which 8x8 b16 sub-matrix lane feeds)
    const int tile = lane >> 3;
    const int l8   = lane & 7;
    const int a_row0  = warp_m + ((tile & 1) << 3) + l8;   // + mi*16
    const int a_usel  = tile >> 1;                         // k16-half select
    const int b_row0  = warp_n + ((tile >> 1) << 3) + l8;  // + nj*16
    const int b_usel  = tile & 1;

    float acc[4][4][4];
#pragma unroll
    for (int i = 0; i < 4; i++)
#pragma unroll
        for (int j = 0; j < 4; j++) {
            acc[i][j][0] = 0.f; acc[i][j][1] = 0.f;
            acc[i][j][2] = 0.f; acc[i][j][3] = 0.f;
        }

    float4 ra[8], rb[8];

// Load one 128x64 fp32 chunk of A and B (8 float4 each per thread).
#define LDG_CHUNK(K0)                                                          \
    _Pragma("unroll")                                                          \
    for (int j = 0; j < 8; j++) {                                              \
        int idx = tid + 256 * j;                                               \
        int row = idx >> 4, seg = idx & 15;                                    \
        ra[j] = *(const float4*)(A  + (size_t)row * lda + (K0) + seg * 4);     \
        rb[j] = *(const float4*)(Bm + (size_t)row * ldb + (K0) + seg * 4);     \
    }

// Split to fp16 hi/lo + swizzled 8B stores into stage ST (char* base).
#define STS_CHUNK(ST)                                                          \
    _Pragma("unroll")                                                          \
    for (int j = 0; j < 8; j++) {                                              \
        int idx = tid + 256 * j;                                               \
        int row = idx >> 4, seg = idx & 15;                                    \
        uint32_t off = ((uint32_t)row << 7) | ((uint32_t)seg << 3);            \
        off ^= ((uint32_t)(row & 7) << 4);                                     \
        uint2 h, l;                                                            \
        split4(ra[j], h, l);                                                   \
        *(uint2*)((ST) + OFF_AHI + off) = h;                                   \
        *(uint2*)((ST) + OFF_ALO + off) = l;                                   \
        split4(rb[j], h, l);                                                   \
        *(uint2*)((ST) + OFF_BHI + off) = h;                                   \
        *(uint2*)((ST) + OFF_BLO + off) = l;                                   \
    }

    // Prologue: chunk 0 -> stage 0
    LDG_CHUNK(0)
    STS_CHUNK(smem)
    __syncthreads();

    const int nc = K / 64;

    for (int i = 0; i < nc; i++) {
        const uint32_t st = sb + (uint32_t)(i & 1) * STAGE_BYTES;

        if (i + 1 < nc) { LDG_CHUNK((i + 1) * 64) }

        // Compute chunk i: 4 k16-slices
#pragma unroll
        for (int ks = 0; ks < 4; ks++) {
            uint32_t ah[4][4], al[4][4], bh[4][2], bl[4][2];
#pragma unroll
            for (int mi = 0; mi < 4; mi++) {
                int row = a_row0 + mi * 16;
                uint32_t off = ((uint32_t)row << 7)
                             | ((uint32_t)((ks * 2 + a_usel) << 4) ^ ((uint32_t)(row & 7) << 4));
                LDSM4(ah[mi][0], ah[mi][1], ah[mi][2], ah[mi][3],
                      st + OFF_AHI + off);
                LDSM4(al[mi][0], al[mi][1], al[mi][2], al[mi][3],
                      st + OFF_ALO + off);
            }
#pragma unroll
            for (int nj = 0; nj < 2; nj++) {
                int row = b_row0 + nj * 16;
                uint32_t off = ((uint32_t)row << 7)
                             | ((uint32_t)((ks * 2 + b_usel) << 4) ^ ((uint32_t)(row & 7) << 4));
                LDSM4(bh[nj * 2][0], bh[nj * 2][1], bh[nj * 2 + 1][0], bh[nj * 2 + 1][1],
                      st + OFF_BHI + off);
                LDSM4(bl[nj * 2][0], bl[nj * 2][1], bl[nj * 2 + 1][0], bl[nj * 2 + 1][1],
                      st + OFF_BLO + off);
            }
            // term-outermost: same-accumulator MMAs are 16 apart
#pragma unroll
            for (int mi = 0; mi < 4; mi++)
#pragma unroll
                for (int ni = 0; ni < 4; ni++)
                    MMA_F16(acc[mi][ni], ah[mi], bh[ni]);
#pragma unroll
            for (int mi = 0; mi < 4; mi++)
#pragma unroll
                for (int ni = 0; ni < 4; ni++)
                    MMA_F16(acc[mi][ni], ah[mi], bl[ni]);
#pragma unroll
            for (int mi = 0; mi < 4; mi++)
#pragma unroll
                for (int ni = 0; ni < 4; ni++)
                    MMA_F16(acc[mi][ni], al[mi], bh[ni]);
        }

        if (i + 1 < nc) {
            char* stn = smem + ((i + 1) & 1) * STAGE_BYTES;
            STS_CHUNK(stn)
            __syncthreads();
        }
    }

    // Epilogue: write accumulators (c0,c1 @ row, c2,c3 @ row+8)
    const int erow = warp_m + (lane >> 2);
    const int ecol = warp_n + 2 * (lane & 3);
#pragma unroll
    for (int mi = 0; mi < 4; mi++) {
#pragma unroll
        for (int ni = 0; ni < 4; ni++) {
            float* cp = C + (size_t)(erow + mi * 16) * ldc + ecol + ni * 8;
            *(float2*)cp = make_float2(acc[mi][ni][0], acc[mi][ni][1]);
            *(float2*)(cp + (size_t)8 * ldc) = make_float2(acc[mi][ni][2], acc[mi][ni][3]);
        }
    }
}

// ---------------------------------------------------------------- transpose
// vT[b][d][s] = src[b][s][d]

__global__ void transpose_bsd(const float* __restrict__ src, float* __restrict__ dst)
{
    __shared__ float t[32][33];
    const int b = blockIdx.z;
    const int s0 = blockIdx.x * 32;
    const int d0 = blockIdx.y * 32;
    const float* sp = src + (size_t)b * S_ * D_;
    float* dp = dst + (size_t)b * D_ * S_;
    const int tx = threadIdx.x, ty = threadIdx.y;
#pragma unroll
    for (int i = 0; i < 32; i += 8)
        t[ty + i][tx] = sp[(size_t)(s0 + ty + i) * D_ + d0 + tx];
    __syncthreads();
#pragma unroll
    for (int i = 0; i < 32; i += 8)
        dp[(size_t)(d0 + ty + i) * S_ + s0 + tx] = t[tx][ty + i];
}

// ---------------------------------------------------------------- softmax

__global__ void softmax_rows(float* __restrict__ w)
{
    __shared__ float redm[8];
    __shared__ float reds[8];
    const int tid  = threadIdx.x;
    const int lane = tid & 31;
    const int wid  = tid >> 5;
    float* p = w + (size_t)blockIdx.x * S_;

    float4 v0 = *(const float4*)(p + tid * 4);
    float4 v1 = *(const float4*)(p + 1024 + tid * 4);

    float mx = fmaxf(fmaxf(fmaxf(v0.x, v0.y), fmaxf(v0.z, v0.w)),
                     fmaxf(fmaxf(v1.x, v1.y), fmaxf(v1.z, v1.w)));
#pragma unroll
    for (int o = 16; o; o >>= 1)
        mx = fmaxf(mx, __shfl_xor_sync(0xffffffffu, mx, o));
    if (lane == 0) redm[wid] = mx;
    __syncthreads();
    if (tid < 32) {
        float m = (tid < 8) ? redm[tid] : -3.402823466e38f;
#pragma unroll
        for (int o = 4; o; o >>= 1)
            m = fmaxf(m, __shfl_xor_sync(0xffffffffu, m, o));
        if (tid == 0) redm[0] = m;
    }
    __syncthreads();
    const float bm = redm[0];

    v0.x = __expf(v0.x - bm); v0.y = __expf(v0.y - bm);
    v0.z = __expf(v0.z - bm); v0.w = __expf(v0.w - bm);
    v1.x = __expf(v1.x - bm); v1.y = __expf(v1.y - bm);
    v1.z = __expf(v1.z - bm); v1.w = __expf(v1.w - bm);

    float sm = v0.x + v0.y + v0.z + v0.w + v1.x + v1.y + v1.z + v1.w;
#pragma unroll
    for (int o = 16; o; o >>= 1)
        sm += __shfl_xor_sync(0xffffffffu, sm, o);
    if (lane == 0) reds[wid] = sm;
    __syncthreads();
    if (tid < 32) {
        float t = (tid < 8) ? reds[tid] : 0.0f;
#pragma unroll
        for (int o = 4; o; o >>= 1)
            t += __shfl_xor_sync(0xffffffffu, t, o);
        if (tid == 0) reds[0] = t;
    }
    __syncthreads();
    const float inv = 1.0f / reds[0];

    v0.x *= inv; v0.y *= inv; v0.z *= inv; v0.w *= inv;
    v1.x *= inv; v1.y *= inv; v1.z *= inv; v1.w *= inv;
    *(float4*)(p + tid * 4)        = v0;
    *(float4*)(p + 1024 + tid * 4) = v1;
}

// ---------------------------------------------------------------- launch

extern "C" void kernel_launch(void* const* d_in, const int* in_sizes, int n_in,
                              void* d_out, int out_size)
{
    const float* trg = (const float*)d_in[0];   // (B, T, D)
    const float* src = (const float*)d_in[1];   // (B, S, D)
    float* ctx = (float*)d_out;                           // (B, T, D)
    float* wts = (float*)d_out + (size_t)B_ * T_ * D_;    // (B, T, S)

    void* vTp = nullptr;
    cudaGetSymbolAddress(&vTp, g_vT);
    float* vT = (float*)vTp;

    cudaFuncSetAttribute(gemm_f16x3,
                         cudaFuncAttributeMaxDynamicSharedMemorySize, SMEM_TOTAL);

    // 1) vT = transpose(src)
    transpose_bsd<<<dim3(S_ / 32, D_ / 32, B_), dim3(32, 8)>>>(src, vT);

    // 2) scores = trg @ src^T   (A=trg [T,D], B=src [S,D], both K-major)
    gemm_f16x3<<<dim3(S_ / 128, T_ / 128, B_), 256, SMEM_TOTAL>>>(
        trg, src, wts, D_, D_, S_, D_,
        (size_t)T_ * D_, (size_t)S_ * D_, (size_t)T_ * S_);

    // 3) softmax rows in place
    softmax_rows<<<B_ * T_, 256>>>(wts);

    // 4) ctx = wts @ vT^T   (A=wts [T,S], B=vT [D,S], both K-major)
    gemm_f16x3<<<dim3(D_ / 128, T_ / 128, B_), 256, SMEM_TOTAL>>>(
        wts, vT, ctx, S_, S_, D_, S_,
        (size_t)T_ * S_, (size_t)D_ * S_, (size_t)T_ * D_);
}